// round 1
// baseline (speedup 1.0000x reference)
#include <cuda_runtime.h>
#include <cstdint>

#define NX 256
#define NU 32
#define NY 32
#define BATCH 16
#define TLEN 8192
#define LCH 128
#define NCH (TLEN / LCH)   // 64 chunks

// Persistent device scratch (no allocations allowed in kernel_launch)
__device__ float g_Bz[NX * NU];          // Bz[n][u] = (Q^T Bmat)[n][u]
__device__ float g_CzT[NX * NY];         // CzT[n][y] = (C Q)[y][n]
__device__ float g_z0[BATCH * NX];       // z0[b][n] = (x0 Q)[b][n]
__device__ float g_lamL[NX];             // lam^LCH
__device__ float g_F[BATCH * NCH * NX];  // per-chunk local finals
__device__ float g_S[BATCH * NCH * NX];  // carries entering each chunk
__device__ float g_V[(size_t)BATCH * TLEN * NX];  // v = u @ Bz^T  (134 MB)

// ---------------------------------------------------------------------------
// K0: prep — Bz, CzT, z0, lam^L
// ---------------------------------------------------------------------------
__global__ void k_prep(const float* __restrict__ x0, const float* __restrict__ Q,
                       const float* __restrict__ lam, const float* __restrict__ Bm,
                       const float* __restrict__ Cin) {
    int idx = blockIdx.x * blockDim.x + threadIdx.x;
    const int tBz = NX * NU;                 // 8192
    const int tCz = tBz + NY * NX;           // +8192
    const int tZ0 = tCz + BATCH * NX;        // +4096
    const int total = tZ0 + NX;              // +256
    for (; idx < total; idx += gridDim.x * blockDim.x) {
        if (idx < tBz) {
            int n = idx / NU, uu = idx % NU;
            float s = 0.f;
            for (int k = 0; k < NX; k++) s = fmaf(Q[k * NX + n], Bm[k * NU + uu], s);
            g_Bz[idx] = s;
        } else if (idx < tCz) {
            int i = idx - tBz;
            int yy = i / NX, n = i % NX;
            float s = 0.f;
            for (int k = 0; k < NX; k++) s = fmaf(Cin[yy * NX + k], Q[k * NX + n], s);
            g_CzT[n * NY + yy] = s;
        } else if (idx < tZ0) {
            int i = idx - tCz;
            int b = i / NX, n = i % NX;
            float s = 0.f;
            for (int k = 0; k < NX; k++) s = fmaf(x0[b * NX + k], Q[k * NX + n], s);
            g_z0[i] = s;
        } else {
            int n = idx - tZ0;
            float p = lam[n];
            #pragma unroll
            for (int j = 0; j < 7; j++) p = p * p;   // lam^128
            g_lamL[n] = p;
        }
    }
}

// ---------------------------------------------------------------------------
// K1: per chunk — compute v = Bz @ u_t (store to g_V), local scan final f_c
// ---------------------------------------------------------------------------
__global__ void __launch_bounds__(256) k_vscan(const float* __restrict__ u,
                                               const float* __restrict__ lam) {
    const int c = blockIdx.x, b = blockIdx.y, n = threadIdx.x;
    __shared__ float su[LCH * NU];  // 16 KB

    const float* ub = u + ((size_t)b * TLEN + (size_t)c * LCH) * NU;
    for (int i = n; i < LCH * NU / 4; i += 256)
        ((float4*)su)[i] = ((const float4*)ub)[i];

    float bz[NU];
    #pragma unroll
    for (int j = 0; j < NU; j++) bz[j] = g_Bz[n * NU + j];
    const float lam_n = lam[n];
    float z = (c == 0) ? g_z0[b * NX + n] : 0.f;
    __syncthreads();

    float* Vout = g_V + ((size_t)(b * TLEN + c * LCH)) * NX + n;
    #pragma unroll 4
    for (int t = 0; t < LCH; t++) {
        const float* ut = su + t * NU;
        float v = 0.f;
        #pragma unroll
        for (int j = 0; j < NU; j += 4) {
            float4 q = *(const float4*)(ut + j);
            v = fmaf(bz[j + 0], q.x, v);
            v = fmaf(bz[j + 1], q.y, v);
            v = fmaf(bz[j + 2], q.z, v);
            v = fmaf(bz[j + 3], q.w, v);
        }
        Vout[(size_t)t * NX] = v;
        z = fmaf(lam_n, z, v);
    }
    g_F[(b * NCH + c) * NX + n] = z;
}

// ---------------------------------------------------------------------------
// K2: cross-chunk carry scan  S_0 = 0; S_c = lam^L * S_{c-1} + f_{c-1}
// ---------------------------------------------------------------------------
__global__ void __launch_bounds__(256) k_carry() {
    const int b = blockIdx.x, n = threadIdx.x;
    const float lamLn = g_lamL[n];
    float s = 0.f;
    g_S[(b * NCH + 0) * NX + n] = 0.f;
    #pragma unroll 8
    for (int c = 1; c < NCH; c++) {
        s = fmaf(lamLn, s, g_F[(b * NCH + c - 1) * NX + n]);
        g_S[(b * NCH + c) * NX + n] = s;
    }
}

// ---------------------------------------------------------------------------
// K3: per chunk — in-smem scan from stored v with correct carry, then
//     Y = Zprev @ Cz^T + U @ D^T  (fused projection from shared memory)
// ---------------------------------------------------------------------------
__global__ void __launch_bounds__(256) k_out(const float* __restrict__ u,
                                             const float* __restrict__ lam,
                                             const float* __restrict__ Dm,
                                             float* __restrict__ y) {
    extern __shared__ float sm[];
    float* Zs  = sm;                 // LCH*NX   = 32768 floats (128 KB)
    float* su  = Zs + LCH * NX;      // LCH*NU   = 4096 floats  (16 KB)
    float* sCz = su + LCH * NU;      // NX*NY    = 8192 floats  (32 KB)
    float* sDT = sCz + NX * NY;      // NU*NY    = 1024 floats  (4 KB)

    const int c = blockIdx.x, b = blockIdx.y, tid = threadIdx.x;

    // Stage v chunk into Zs (coalesced bulk copy, high MLP)
    const float4* V4 = (const float4*)(g_V + ((size_t)(b * TLEN + c * LCH)) * NX);
    for (int i = tid; i < LCH * NX / 4; i += 256) ((float4*)Zs)[i] = V4[i];
    // Stage u chunk
    const float* ub = u + ((size_t)b * TLEN + (size_t)c * LCH) * NU;
    for (int i = tid; i < LCH * NU / 4; i += 256)
        ((float4*)su)[i] = ((const float4*)ub)[i];
    // Stage CzT
    for (int i = tid; i < NX * NY / 4; i += 256)
        ((float4*)sCz)[i] = ((const float4*)g_CzT)[i];
    // Stage D transposed: sDT[j][y] = D[y][j]
    for (int i = tid; i < NU * NY; i += 256) {
        int j = i / NY, yy = i % NY;
        sDT[i] = Dm[yy * NU + j];
    }
    __syncthreads();

    // In-place scan: Zs[t][n] becomes z_prev[t][n]
    {
        const int n = tid;
        const float lam_n = lam[n];
        float z = (c == 0) ? g_z0[b * NX + n] : g_S[(b * NCH + c) * NX + n];
        #pragma unroll 4
        for (int t = 0; t < LCH; t++) {
            float v = Zs[t * NX + n];
            Zs[t * NX + n] = z;
            z = fmaf(lam_n, z, v);
        }
    }
    __syncthreads();

    // Projection: warp w owns 16 timesteps, lane owns output index y
    const int w = tid >> 5, lane = tid & 31;
    const int t0 = w * (LCH / 8);
    float dcol[NU];
    #pragma unroll
    for (int j = 0; j < NU; j++) dcol[j] = sDT[j * NY + lane];

    float acc[LCH / 8];
    #pragma unroll
    for (int tt = 0; tt < LCH / 8; tt++) acc[tt] = 0.f;

    for (int n0 = 0; n0 < NX; n0 += 4) {
        float cz0 = sCz[(n0 + 0) * NY + lane];
        float cz1 = sCz[(n0 + 1) * NY + lane];
        float cz2 = sCz[(n0 + 2) * NY + lane];
        float cz3 = sCz[(n0 + 3) * NY + lane];
        #pragma unroll
        for (int tt = 0; tt < LCH / 8; tt++) {
            float4 zv = *(const float4*)&Zs[(t0 + tt) * NX + n0];
            acc[tt] = fmaf(zv.x, cz0,
                      fmaf(zv.y, cz1,
                      fmaf(zv.z, cz2,
                      fmaf(zv.w, cz3, acc[tt]))));
        }
    }
    #pragma unroll
    for (int j0 = 0; j0 < NU; j0 += 4) {
        #pragma unroll
        for (int tt = 0; tt < LCH / 8; tt++) {
            float4 uv = *(const float4*)&su[(t0 + tt) * NU + j0];
            acc[tt] = fmaf(uv.x, dcol[j0 + 0],
                      fmaf(uv.y, dcol[j0 + 1],
                      fmaf(uv.z, dcol[j0 + 2],
                      fmaf(uv.w, dcol[j0 + 3], acc[tt]))));
        }
    }

    float* yb = y + ((size_t)(b * TLEN + c * LCH + t0)) * NY + lane;
    #pragma unroll
    for (int tt = 0; tt < LCH / 8; tt++) yb[(size_t)tt * NY] = acc[tt];
}

// ---------------------------------------------------------------------------
extern "C" void kernel_launch(void* const* d_in, const int* in_sizes, int n_in,
                              void* d_out, int out_size) {
    const float* x0  = (const float*)d_in[0];
    const float* u   = (const float*)d_in[1];
    const float* Q   = (const float*)d_in[2];
    const float* lam = (const float*)d_in[3];
    const float* Bm  = (const float*)d_in[4];
    const float* Cin = (const float*)d_in[5];
    const float* Dm  = (const float*)d_in[6];
    float* y = (float*)d_out;

    const int smem_k3 = (LCH * NX + LCH * NU + NX * NY + NU * NY) * 4;  // 184320 B
    cudaFuncSetAttribute(k_out, cudaFuncAttributeMaxDynamicSharedMemorySize, smem_k3);

    k_prep<<<82, 256>>>(x0, Q, lam, Bm, Cin);
    k_vscan<<<dim3(NCH, BATCH), 256>>>(u, lam);
    k_carry<<<BATCH, 256>>>();
    k_out<<<dim3(NCH, BATCH), 256, smem_k3>>>(u, lam, Dm, y);
}